// round 2
// baseline (speedup 1.0000x reference)
#include <cuda_runtime.h>
#include <math.h>

#define HW      65536
#define OUT_C   128
#define NCH     256   // 2*OUT_C
#define EPSBN   1e-5f
#define NSTATB  128   // stats blocks

// ---------------- per-channel constant pack ----------------
struct __align__(16) ChConst {
    float aAx, aAy, aAc, bAx, bAy, bAc;     // angle affine coeffs
    float2 P[4], Q[4], R[4], T[4];          // u = ca*P + sa*Q + cb*R + sb*T
    float  Md[4];                           // diag of M (real)
    float2 Moff[6];                         // (2*Re(Mjk), -2*Im(Mjk)) for j<k
    float  pad[10];                         // pad to 64 floats
};

__device__ ChConst g_ch[OUT_C];
__device__ float   g_part[NSTATB * 5];

// ---------------- kernel 1: image moments (deterministic tree reduce) ----------
__global__ void stats_kernel(const float* __restrict__ coords) {
    const float* x = coords;        // batch 0, channel 0
    const float* y = coords + HW;   // batch 0, channel 1
    float sx = 0.f, sy = 0.f, sxx = 0.f, syy = 0.f, sxy = 0.f;
    for (int p = blockIdx.x * blockDim.x + threadIdx.x; p < HW;
         p += gridDim.x * blockDim.x) {
        float xv = x[p], yv = y[p];
        sx += xv; sy += yv;
        sxx = fmaf(xv, xv, sxx);
        syy = fmaf(yv, yv, syy);
        sxy = fmaf(xv, yv, sxy);
    }
    #pragma unroll
    for (int off = 16; off > 0; off >>= 1) {
        sx  += __shfl_down_sync(0xffffffffu, sx,  off);
        sy  += __shfl_down_sync(0xffffffffu, sy,  off);
        sxx += __shfl_down_sync(0xffffffffu, sxx, off);
        syy += __shfl_down_sync(0xffffffffu, syy, off);
        sxy += __shfl_down_sync(0xffffffffu, sxy, off);
    }
    __shared__ float sh[5][8];
    int w = threadIdx.x >> 5, l = threadIdx.x & 31;
    if (l == 0) { sh[0][w]=sx; sh[1][w]=sy; sh[2][w]=sxx; sh[3][w]=syy; sh[4][w]=sxy; }
    __syncthreads();
    if (threadIdx.x < 5) {
        float s = 0.f;
        #pragma unroll
        for (int i = 0; i < 8; ++i) s += sh[threadIdx.x][i];
        g_part[blockIdx.x * 5 + threadIdx.x] = s;
    }
}

// ---------------- kernel 2: per-channel circuit precompute --------------------
struct cpx { float r, i; };
__device__ __forceinline__ cpx cmul(cpx a, cpx b){ return {a.r*b.r - a.i*b.i, a.r*b.i + a.i*b.r}; }
__device__ __forceinline__ cpx cadd(cpx a, cpx b){ return {a.r + b.r, a.i + b.i}; }
__device__ __forceinline__ cpx csub(cpx a, cpx b){ return {a.r - b.r, a.i - b.i}; }
__device__ __forceinline__ cpx cconj(cpx a){ return {a.r, -a.i}; }

// Build layer unitary A_s (4x4) for channel o from params.
// psi <- CNOT * emb1(U(s,j,1)) * emb0(U(s,j,0)) * psi, for j = 0,1.
__device__ void build_layer(const float* qp, int s, int o, cpx A[4][4]) {
    for (int i = 0; i < 4; ++i)
        for (int j = 0; j < 4; ++j)
            A[i][j] = { (i == j) ? 1.f : 0.f, 0.f };
    for (int j = 0; j < 2; ++j) {
        for (int w = 0; w < 2; ++w) {
            const float* p = qp + (((s*2 + j) * NCH) + o*2 + w) * 3;
            float th = p[0], ph = p[1], lm = p[2];
            float st, ct; sincosf(0.5f * th, &st, &ct);
            float slm, clm; sincosf(lm, &slm, &clm);
            float sph, cph; sincosf(ph, &sph, &cph);
            float spl, cpl; sincosf(ph + lm, &spl, &cpl);
            cpx U00 = { ct, 0.f };
            cpx U01 = { -clm * st, -slm * st };
            cpx U10 = {  cph * st,  sph * st };
            cpx U11 = {  cpl * ct,  spl * ct };
            if (w == 0) { // wire 0: rows (q, 2+q)
                for (int q = 0; q < 2; ++q)
                    for (int c = 0; c < 4; ++c) {
                        cpx r0 = A[q][c], r1 = A[2+q][c];
                        A[q][c]   = cadd(cmul(U00, r0), cmul(U01, r1));
                        A[2+q][c] = cadd(cmul(U10, r0), cmul(U11, r1));
                    }
            } else {      // wire 1: rows (2q, 2q+1)
                for (int q = 0; q < 2; ++q)
                    for (int c = 0; c < 4; ++c) {
                        cpx r0 = A[2*q][c], r1 = A[2*q+1][c];
                        A[2*q][c]   = cadd(cmul(U00, r0), cmul(U01, r1));
                        A[2*q+1][c] = cadd(cmul(U10, r0), cmul(U11, r1));
                    }
            }
        }
        // CNOT: swap rows 2 and 3
        for (int c = 0; c < 4; ++c) { cpx t = A[2][c]; A[2][c] = A[3][c]; A[3][c] = t; }
    }
}

__global__ void precompute_kernel(const float* __restrict__ freq,
                                  const float* __restrict__ qp,
                                  const float* __restrict__ bnw,
                                  const float* __restrict__ bnb) {
    __shared__ float stats[5];
    if (threadIdx.x < 5) {
        double s = 0.0;
        for (int i = 0; i < NSTATB; ++i) s += (double)g_part[i*5 + threadIdx.x];
        stats[threadIdx.x] = (float)s;
    }
    __syncthreads();
    int o = threadIdx.x;
    if (o >= OUT_C) return;

    const float N  = (float)HW;
    float mx  = stats[0] / N, my = stats[1] / N;
    float Sxx = stats[2] / N - mx * mx;
    float Syy = stats[3] / N - my * my;
    float Sxy = stats[4] / N - mx * my;

    // BN-folded affine per sub-channel: xn = gx*x + gy*y + gc
    float gx[2], gy[2], gc[2];
    #pragma unroll
    for (int w = 0; w < 2; ++w) {
        int m = 2*o + w;
        float f0 = freq[m*2 + 0], f1 = freq[m*2 + 1];
        float mean = f0 * mx + f1 * my;
        float var  = f0*f0*Sxx + 2.f*f0*f1*Sxy + f1*f1*Syy;
        float s    = bnw[m] / sqrtf(var + EPSBN);
        gx[w] = f0 * s; gy[w] = f1 * s; gc[w] = bnb[m] - mean * s;
    }

    ChConst cc;
    cc.aAx = 0.5f*(gx[0]+gx[1]); cc.aAy = 0.5f*(gy[0]+gy[1]); cc.aAc = 0.5f*(gc[0]+gc[1]);
    cc.bAx = 0.5f*(gx[0]-gx[1]); cc.bAy = 0.5f*(gy[0]-gy[1]); cc.bAc = 0.5f*(gc[0]-gc[1]);

    cpx A0[4][4], A1[4][4], A2[4][4];
    build_layer(qp, 0, o, A0);
    build_layer(qp, 1, o, A1);
    build_layer(qp, 2, o, A2);

    cpx v0[4];
    for (int j = 0; j < 4; ++j) v0[j] = A0[j][0];
    cpx C[4][4];
    for (int j = 0; j < 4; ++j)
        for (int k = 0; k < 4; ++k) C[j][k] = cmul(A1[j][k], v0[k]);

    // u = ca*P + sa*Q + cb*R + sb*T, with Q = i(C3-C0), T = i(C2-C1)
    for (int j = 0; j < 4; ++j) {
        cpx P  = cadd(C[j][0], C[j][3]);
        cpx dq = csub(C[j][3], C[j][0]);
        cpx R  = cadd(C[j][1], C[j][2]);
        cpx dt = csub(C[j][2], C[j][1]);
        cc.P[j] = make_float2(P.r, P.i);
        cc.Q[j] = make_float2(-dq.i, dq.r);
        cc.R[j] = make_float2(R.r, R.i);
        cc.T[j] = make_float2(-dt.i, dt.r);
    }

    // M = A2^H (Z x I) A2, Z x I = diag(1,1,-1,-1)
    cpx M[4][4];
    for (int j = 0; j < 4; ++j)
        for (int k = 0; k < 4; ++k) {
            cpx acc = {0.f, 0.f};
            for (int l = 0; l < 4; ++l) {
                float z = (l < 2) ? 1.f : -1.f;
                cpx t = cmul(cconj(A2[l][j]), A2[l][k]);
                acc.r += z * t.r; acc.i += z * t.i;
            }
            M[j][k] = acc;
        }
    for (int j = 0; j < 4; ++j) cc.Md[j] = M[j][j].r;
    int idx = 0;
    for (int j = 0; j < 4; ++j)
        for (int k = j+1; k < 4; ++k) {
            cc.Moff[idx] = make_float2(2.f * M[j][k].r, -2.f * M[j][k].i);
            idx++;
        }
    #pragma unroll
    for (int t = 0; t < 10; ++t) cc.pad[t] = 0.f;

    g_ch[o] = cc;
}

// ---------------- per-pixel evaluation ----------------------------------------
__device__ __forceinline__ float eval_point(const ChConst& cc, float xv, float yv) {
    float a = fmaf(cc.aAx, xv, fmaf(cc.aAy, yv, cc.aAc));
    float b = fmaf(cc.bAx, xv, fmaf(cc.bAy, yv, cc.bAc));
    float sa, ca, sb, cb;
    __sincosf(a, &sa, &ca);
    __sincosf(b, &sb, &cb);

    float ur[4], ui[4];
    #pragma unroll
    for (int j = 0; j < 4; ++j) {
        ur[j] = fmaf(ca, cc.P[j].x, fmaf(sa, cc.Q[j].x, fmaf(cb, cc.R[j].x, sb * cc.T[j].x)));
        ui[j] = fmaf(ca, cc.P[j].y, fmaf(sa, cc.Q[j].y, fmaf(cb, cc.R[j].y, sb * cc.T[j].y)));
    }

    // e = D * u, D = diag(e^{-ia}, e^{-ib}, e^{+ib}, e^{+ia})
    float er[4], ei[4];
    er[0] = fmaf(ca, ur[0],  sa * ui[0]);  ei[0] = fmaf(ca, ui[0], -sa * ur[0]);
    er[1] = fmaf(cb, ur[1],  sb * ui[1]);  ei[1] = fmaf(cb, ui[1], -sb * ur[1]);
    er[2] = fmaf(cb, ur[2], -sb * ui[2]);  ei[2] = fmaf(cb, ui[2],  sb * ur[2]);
    er[3] = fmaf(ca, ur[3], -sa * ui[3]);  ei[3] = fmaf(ca, ui[3],  sa * ur[3]);

    // ev = e^H M e  (|e_j| == |u_j| for diagonal terms)
    float ev = 0.f;
    #pragma unroll
    for (int j = 0; j < 4; ++j)
        ev = fmaf(cc.Md[j], fmaf(ur[j], ur[j], ui[j] * ui[j]), ev);
    int idx = 0;
    #pragma unroll
    for (int j = 0; j < 4; ++j)
        #pragma unroll
        for (int k = j + 1; k < 4; ++k) {
            float tr = fmaf(er[j], er[k],  ei[j] * ei[k]);
            float ti = fmaf(er[j], ei[k], -ei[j] * er[k]);
            ev = fmaf(cc.Moff[idx].x, tr, fmaf(cc.Moff[idx].y, ti, ev));
            idx++;
        }
    return ev;
}

// ---------------- kernel 3: main, float4-vectorized ---------------------------
__global__ void __launch_bounds__(256)
main_kernel(const float4* __restrict__ x4, const float4* __restrict__ y4,
            float4* __restrict__ out4) {
    const int o = blockIdx.y;
    const ChConst cc = g_ch[o];
    const int HW4 = HW / 4;
    float4* __restrict__ o0 = out4 + (size_t)o * HW4;

    for (int g = blockIdx.x * blockDim.x + threadIdx.x; g < HW4;
         g += gridDim.x * blockDim.x) {
        float4 xv = __ldg(x4 + g);
        float4 yv = __ldg(y4 + g);
        float4 r;
        r.x = eval_point(cc, xv.x, yv.x);
        r.y = eval_point(cc, xv.y, yv.y);
        r.z = eval_point(cc, xv.z, yv.z);
        r.w = eval_point(cc, xv.w, yv.w);
        o0[g]                           = r;
        o0[g + (size_t)1 * OUT_C * HW4] = r;
        o0[g + (size_t)2 * OUT_C * HW4] = r;
        o0[g + (size_t)3 * OUT_C * HW4] = r;
    }
}

// ---------------- launch ------------------------------------------------------
extern "C" void kernel_launch(void* const* d_in, const int* in_sizes, int n_in,
                              void* d_out, int out_size) {
    const float* coords = (const float*)d_in[0];   // (4, 2, 256, 256)
    const float* freq   = (const float*)d_in[1];   // (256, 2)
    const float* qp     = (const float*)d_in[2];   // (1, 3, 2, 256, 3)
    const float* bnw    = (const float*)d_in[3];   // (256,)
    const float* bnb    = (const float*)d_in[4];   // (256,)
    float* out = (float*)d_out;                    // (4, 128, 256, 256)

    stats_kernel<<<NSTATB, 256>>>(coords);
    precompute_kernel<<<1, 128>>>(freq, qp, bnw, bnb);

    const float4* x4 = (const float4*)coords;           // batch0 ch0
    const float4* y4 = (const float4*)(coords + HW);    // batch0 ch1
    dim3 grid(16, OUT_C);
    main_kernel<<<grid, 256>>>(x4, y4, (float4*)out);
}